// round 9
// baseline (speedup 1.0000x reference)
#include <cuda_runtime.h>
#include <cuda_fp16.h>
#include <math.h>

#define NBATCH 4096
#define TWO_N  8192
#define DIMK   256
#define INV_TEMP 2.0f
#define QS     256.0f                  // int8 quantization scale
#define EPSCL  (2.0f / 65536.0f)       // INV_TEMP / QS^2

// ---------------- device scratch (no allocs allowed) ----------------
__device__ signed char g_s8[TWO_N * DIMK];    // normalized reps int8*256 (2 MB)
__device__ float    g_pos[TWO_N];             // positive-pair cosine (fp32 exact)
__device__ float    g_scatter[64 * TWO_N];    // per-(row, key) partial sums (2 MB)
__device__ float    g_partial[32];            // finalize partials
__device__ unsigned g_ctr;                    // last-block-done counter

// ---------------- PTX helpers (base sm_103 target only) ----------------
static __device__ __forceinline__ unsigned smem_u32(const void* p) {
    unsigned a;
    asm("{ .reg .u64 t; cvta.to.shared.u64 t, %1; cvt.u32.u64 %0, t; }" : "=r"(a) : "l"(p));
    return a;
}

static __device__ __forceinline__ int q8(float x) {
    int v = __float2int_rn(x);
    return v > 127 ? 127 : (v < -127 ? -127 : v);
}
static __device__ __forceinline__ unsigned pk4(float a, float b, float c, float d) {
    return (unsigned)(q8(a) & 255) | ((unsigned)(q8(b) & 255) << 8) |
           ((unsigned)(q8(c) & 255) << 16) | ((unsigned)(q8(d) & 255) << 24);
}

#define CP_ASYNC16(dst, src) \
    asm volatile("cp.async.cg.shared.global [%0], [%1], 16;" :: "r"(dst), "l"(src) : "memory")
#define CP_ASYNC_COMMIT() asm volatile("cp.async.commit_group;" ::: "memory")

#define LDSM_X4(r0, r1, r2, r3, addr) \
    asm volatile("ldmatrix.sync.aligned.m8n8.x4.shared.b16 {%0,%1,%2,%3}, [%4];" \
        : "=r"(r0), "=r"(r1), "=r"(r2), "=r"(r3) : "r"(addr))

// int8 IMMA: m16n8k32, s32 accumulate
#define MMA_S8(c0, c1, c2, c3, a0, a1, a2, a3, b0, b1) \
    asm volatile("mma.sync.aligned.m16n8k32.row.col.s32.s8.s8.s32 " \
        "{%0,%1,%2,%3}, {%4,%5,%6,%7}, {%8,%9}, {%0,%1,%2,%3};" \
        : "+r"(c0), "+r"(c1), "+r"(c2), "+r"(c3) \
        : "r"(a0), "r"(a1), "r"(a2), "r"(a3), "r"(b0), "r"(b1))

// ---------------- kernel 1: normalize + positive pairs -> int8 ----------------
__global__ void ntx_norm(const float* __restrict__ zis,
                         const float* __restrict__ zjs) {
    if (blockIdx.x == 0 && threadIdx.x == 0) g_ctr = 0;   // reset finalize counter
    int p    = blockIdx.x * 8 + (threadIdx.x >> 5);
    int lane = threadIdx.x & 31;
    const float4* j4 = (const float4*)(zjs + (size_t)p * DIMK);
    const float4* i4 = (const float4*)(zis + (size_t)p * DIMK);
    float4 ja = j4[lane], jb = j4[lane + 32];
    float4 ia = i4[lane], ib = i4[lane + 32];
    float ssj = ja.x*ja.x+ja.y*ja.y+ja.z*ja.z+ja.w*ja.w + jb.x*jb.x+jb.y*jb.y+jb.z*jb.z+jb.w*jb.w;
    float ssi = ia.x*ia.x+ia.y*ia.y+ia.z*ia.z+ia.w*ia.w + ib.x*ib.x+ib.y*ib.y+ib.z*ib.z+ib.w*ib.w;
    float dot = ja.x*ia.x+ja.y*ia.y+ja.z*ia.z+ja.w*ia.w + jb.x*ib.x+jb.y*ib.y+jb.z*ib.z+jb.w*ib.w;
    #pragma unroll
    for (int o = 16; o >= 1; o >>= 1) {
        ssj += __shfl_xor_sync(0xFFFFFFFFu, ssj, o);
        ssi += __shfl_xor_sync(0xFFFFFFFFu, ssi, o);
        dot += __shfl_xor_sync(0xFFFFFFFFu, dot, o);
    }
    float rj = rsqrtf(ssj), ri = rsqrtf(ssi);
    float rnj = rj * QS, rni = ri * QS;
    unsigned* dj = (unsigned*)(g_s8 + (size_t)p * DIMK);
    unsigned* di = (unsigned*)(g_s8 + (size_t)(p + NBATCH) * DIMK);
    dj[lane]      = pk4(ja.x*rnj, ja.y*rnj, ja.z*rnj, ja.w*rnj);
    dj[lane + 32] = pk4(jb.x*rnj, jb.y*rnj, jb.z*rnj, jb.w*rnj);
    di[lane]      = pk4(ia.x*rni, ia.y*rni, ia.z*rni, ia.w*rni);
    di[lane + 32] = pk4(ib.x*rni, ib.y*rni, ib.z*rni, ib.w*rni);
    if (lane == 0) {
        float pos = dot * rj * ri;
        g_pos[p] = pos;
        g_pos[p + NBATCH] = pos;
    }
}

// ---------------- kernel 2: symmetric INT8 IMMA Gram + exp + row/col sums ----
// Upper-triangle tiles (2080). 32 band-pairs (p, 63-p) of 65 tiles, 4 blocks
// each -> grid 128. Tile (I,J): row-sums -> key J, col-sums -> key I (I!=J).
#define SMI   0
#define SMJ   32768
#define BBUF  32768
#define SMEM_TOTAL (32768 * 3)

static __device__ __forceinline__ void map_ij(int g, int p, int n1, int& I, int& J) {
    if (g < n1) { I = p;      J = p + g; }
    else        { I = 63 - p; J = 63 - p + (g - n1); }
}

static __device__ __forceinline__ void load_tile(unsigned dstbase, int band, int tid) {
    const char* src = (const char*)g_s8 + (size_t)band * 128 * 256;
    #pragma unroll
    for (int i = 0; i < 8; i++) {
        int idx = tid + i * 256;
        int row = idx >> 4, u = idx & 15;
        CP_ASYNC16(dstbase + row * 256 + ((u ^ (row & 7)) << 4),
                   src + (size_t)row * 256 + u * 16);
    }
}

__global__ void __launch_bounds__(256, 1) ntx_main() {
    extern __shared__ char smem[];
    unsigned sb = smem_u32(smem);
    __shared__ float s_roww[4][128];
    __shared__ float s_colw[2][128];

    int tid = threadIdx.x, wid = tid >> 5, lane = tid & 31;
    int p = blockIdx.x >> 2, q = blockIdx.x & 3;
    int g0 = (q == 0) ? 0 : q * 16 + 1;
    int L  = (q == 0) ? 17 : 16;
    int n1 = 64 - p;

    int wm = (wid & 1) * 64;
    int wn = (wid >> 1) * 32;
    int trow  = lane >> 2;
    int tcol2 = lane & 3;
    int sw    = lane & 7;
    int rowinA = ((lane >> 3) & 1) * 8 + (lane & 7);
    int kbA    = lane >> 4;
    int rowinB = (lane >> 4) * 8 + (lane & 7);
    int kbB    = (lane >> 3) & 1;

    unsigned abyte[4], bbyte[2];
    #pragma unroll
    for (int mt = 0; mt < 4; mt++) abyte[mt] = (unsigned)((wm + mt * 16 + rowinA) * 256);
    #pragma unroll
    for (int ng = 0; ng < 2; ng++)  bbyte[ng] = (unsigned)((wn + ng * 16 + rowinB) * 256);

    int I0, J0; map_ij(g0, p, n1, I0, J0);
    load_tile(sb + SMI, I0, tid);
    load_tile(sb + SMJ, J0, tid);
    CP_ASYNC_COMMIT();
    int curI = I0;

    for (int k = 0; k < L; k++) {
        int I, J; map_ij(g0 + k, p, n1, I, J);
        if (I != curI) {
            load_tile(sb + SMI, I, tid);
            CP_ASYNC_COMMIT();
            curI = I;
        }
        if (k + 1 < L) {
            int In, Jn; map_ij(g0 + k + 1, p, n1, In, Jn);
            load_tile(sb + SMJ + (unsigned)((k + 1) & 1) * BBUF, Jn, tid);
            CP_ASYNC_COMMIT();
            asm volatile("cp.async.wait_group 1;" ::: "memory");
        } else {
            asm volatile("cp.async.wait_group 0;" ::: "memory");
        }
        __syncthreads();

        unsigned curB = sb + SMJ + (unsigned)(k & 1) * BBUF;

        int acc[4][4][4];
        #pragma unroll
        for (int mt = 0; mt < 4; mt++)
            #pragma unroll
            for (int nt = 0; nt < 4; nt++)
                #pragma unroll
                for (int e = 0; e < 4; e++) acc[mt][nt][e] = 0;

        #pragma unroll
        for (int ks = 0; ks < 8; ks++) {
            unsigned koffA = (unsigned)(((ks * 2 + kbA) ^ sw) << 4);
            unsigned koffB = (unsigned)(((ks * 2 + kbB) ^ sw) << 4);
            unsigned a0[4], a1[4], a2[4], a3[4];
            #pragma unroll
            for (int mt = 0; mt < 4; mt++)
                LDSM_X4(a0[mt], a1[mt], a2[mt], a3[mt], sb + SMI + abyte[mt] + koffA);
            unsigned b0[2], b1[2], b2[2], b3[2];
            #pragma unroll
            for (int ng = 0; ng < 2; ng++)
                LDSM_X4(b0[ng], b1[ng], b2[ng], b3[ng], curB + bbyte[ng] + koffB);
            #pragma unroll
            for (int mt = 0; mt < 4; mt++) {
                MMA_S8(acc[mt][0][0], acc[mt][0][1], acc[mt][0][2], acc[mt][0][3],
                       a0[mt], a1[mt], a2[mt], a3[mt], b0[0], b1[0]);
                MMA_S8(acc[mt][1][0], acc[mt][1][1], acc[mt][1][2], acc[mt][1][3],
                       a0[mt], a1[mt], a2[mt], a3[mt], b2[0], b3[0]);
                MMA_S8(acc[mt][2][0], acc[mt][2][1], acc[mt][2][2], acc[mt][2][3],
                       a0[mt], a1[mt], a2[mt], a3[mt], b0[1], b1[1]);
                MMA_S8(acc[mt][3][0], acc[mt][3][1], acc[mt][3][2], acc[mt][3][3],
                       a0[mt], a1[mt], a2[mt], a3[mt], b2[1], b3[1]);
            }
        }

        // epilogue: exp(acc * 2/QS^2), mask self-diagonal, row+col partials
        bool diag = (I == J);
        float rsum[4][2], csum[4][2];
        #pragma unroll
        for (int x = 0; x < 4; x++) { rsum[x][0]=rsum[x][1]=csum[x][0]=csum[x][1]=0.f; }
        #pragma unroll
        for (int mt = 0; mt < 4; mt++) {
            int r0 = wm + mt * 16 + trow;
            #pragma unroll
            for (int nt = 0; nt < 4; nt++) {
                int c0 = wn + nt * 8 + tcol2 * 2;
                float e00 = __expf(EPSCL * (float)acc[mt][nt][0]);
                float e01 = __expf(EPSCL * (float)acc[mt][nt][1]);
                float e10 = __expf(EPSCL * (float)acc[mt][nt][2]);
                float e11 = __expf(EPSCL * (float)acc[mt][nt][3]);
                if (diag) {
                    if (r0 == c0)         e00 = 0.f;
                    if (r0 == c0 + 1)     e01 = 0.f;
                    if (r0 + 8 == c0)     e10 = 0.f;
                    if (r0 + 8 == c0 + 1) e11 = 0.f;
                }
                rsum[mt][0] += e00 + e01;
                rsum[mt][1] += e10 + e11;
                csum[nt][0] += e00 + e10;
                csum[nt][1] += e01 + e11;
            }
        }
        #pragma unroll
        for (int mt = 0; mt < 4; mt++)
            #pragma unroll
            for (int hf = 0; hf < 2; hf++) {
                float v = rsum[mt][hf];
                v += __shfl_xor_sync(0xFFFFFFFFu, v, 1);
                v += __shfl_xor_sync(0xFFFFFFFFu, v, 2);
                if ((lane & 3) == 0)
                    s_roww[wid >> 1][wm + mt * 16 + hf * 8 + trow] = v;
            }
        #pragma unroll
        for (int nt = 0; nt < 4; nt++)
            #pragma unroll
            for (int j = 0; j < 2; j++) {
                float v = csum[nt][j];
                v += __shfl_xor_sync(0xFFFFFFFFu, v, 4);
                v += __shfl_xor_sync(0xFFFFFFFFu, v, 8);
                v += __shfl_xor_sync(0xFFFFFFFFu, v, 16);
                if (lane < 4)
                    s_colw[wid & 1][wn + nt * 8 + lane * 2 + j] = v;
            }
        __syncthreads();

        if (tid < 128) {
            float rv = s_roww[0][tid] + s_roww[1][tid] + s_roww[2][tid] + s_roww[3][tid];
            g_scatter[(size_t)J * TWO_N + I * 128 + tid] = rv;
            if (!diag) {
                float cv = s_colw[0][tid] + s_colw[1][tid];
                g_scatter[(size_t)I * TWO_N + J * 128 + tid] = cv;
            }
        }
    }
}

// ---------------- kernel 3: per-row loss partials + last-block finalize ----
__global__ void ntx_fin(float* __restrict__ out) {
    __shared__ float sh[256];
    __shared__ int s_last;
    int tid = threadIdx.x;
    int i = blockIdx.x * 256 + tid;
    float rs = 0.f;
    #pragma unroll
    for (int k = 0; k < 64; k++) rs += g_scatter[(size_t)k * TWO_N + i];
    sh[tid] = logf(rs) - INV_TEMP * g_pos[i];
    __syncthreads();
    for (int s = 128; s >= 1; s >>= 1) {
        if (tid < s) sh[tid] += sh[tid + s];
        __syncthreads();
    }
    if (tid == 0) {
        g_partial[blockIdx.x] = sh[0];
        __threadfence();
        unsigned old = atomicAdd(&g_ctr, 1u);
        s_last = (old == 31u);
    }
    __syncthreads();
    if (s_last && tid < 32) {
        float v = g_partial[tid];
        #pragma unroll
        for (int o = 16; o >= 1; o >>= 1) v += __shfl_xor_sync(0xFFFFFFFFu, v, o);
        if (tid == 0) out[0] = v / (float)TWO_N;
    }
}

extern "C" void kernel_launch(void* const* d_in, const int* in_sizes, int n_in,
                              void* d_out, int out_size) {
    const float* zis = (const float*)d_in[0];
    const float* zjs = (const float*)d_in[1];
    float* out = (float*)d_out;
    (void)in_sizes; (void)n_in; (void)out_size;

    cudaFuncSetAttribute(ntx_main, cudaFuncAttributeMaxDynamicSharedMemorySize,
                         SMEM_TOTAL);

    ntx_norm<<<NBATCH / 8, 256>>>(zis, zjs);
    ntx_main<<<128, 256, SMEM_TOTAL>>>();
    ntx_fin<<<32, 256>>>(out);
}

// round 10
// speedup vs baseline: 2.3373x; 2.3373x over previous
#include <cuda_runtime.h>
#include <cuda_fp16.h>
#include <math.h>

#define NBATCH 4096
#define TWO_N  8192
#define DIMK   256
#define INV_TEMP 2.0f
#define QSCALE 16.0f            // fp8 quantization scale
#define EPSCL  (2.0f / 256.0f)  // epilogue: INV_TEMP / QSCALE^2

// ---------------- device scratch (no allocs allowed) ----------------
__device__ unsigned char g_fp8[TWO_N * DIMK]; // normalized reps e4m3*16 (2 MB)
__device__ float    g_pos[TWO_N];             // positive-pair cosine (fp32 exact)
__device__ float    g_scatter[64 * TWO_N];    // per-(row, key) partial sums (2 MB)
__device__ float    g_partial[32];            // finalize partials
__device__ unsigned g_ctr;                    // last-block-done counter

// ---------------- PTX helpers (base sm_103 target only) ----------------
static __device__ __forceinline__ unsigned smem_u32(const void* p) {
    unsigned a;
    asm("{ .reg .u64 t; cvta.to.shared.u64 t, %1; cvt.u32.u64 %0, t; }" : "=r"(a) : "l"(p));
    return a;
}

// pack two f32 -> e4m3x2 (lo in low byte)
static __device__ __forceinline__ unsigned short pk_e4m3(float lo, float hi) {
    unsigned short r;
    asm("cvt.rn.satfinite.e4m3x2.f32 %0, %2, %1;" : "=h"(r) : "f"(lo), "f"(hi));
    return r;
}

#define CP_ASYNC16(dst, src) \
    asm volatile("cp.async.cg.shared.global [%0], [%1], 16;" :: "r"(dst), "l"(src) : "memory")
#define CP_ASYNC_COMMIT() asm volatile("cp.async.commit_group;" ::: "memory")

#define LDSM_X4(r0, r1, r2, r3, addr) \
    asm volatile("ldmatrix.sync.aligned.m8n8.x4.shared.b16 {%0,%1,%2,%3}, [%4];" \
        : "=r"(r0), "=r"(r1), "=r"(r2), "=r"(r3) : "r"(addr))

// fp8 e4m3 MMA: m16n8k32, fp32 accumulate
#define MMA_FP8(c0, c1, c2, c3, a0, a1, a2, a3, b0, b1) \
    asm volatile("mma.sync.aligned.m16n8k32.row.col.f32.e4m3.e4m3.f32 " \
        "{%0,%1,%2,%3}, {%4,%5,%6,%7}, {%8,%9}, {%0,%1,%2,%3};" \
        : "+f"(c0), "+f"(c1), "+f"(c2), "+f"(c3) \
        : "r"(a0), "r"(a1), "r"(a2), "r"(a3), "r"(b0), "r"(b1))

// ---------------- kernel 1: normalize + positive pairs -> fp8 ----------------
__global__ void ntx_norm(const float* __restrict__ zis,
                         const float* __restrict__ zjs) {
    if (blockIdx.x == 0 && threadIdx.x == 0) g_ctr = 0;   // reset finalize counter
    int p    = blockIdx.x * 8 + (threadIdx.x >> 5);
    int lane = threadIdx.x & 31;
    const float4* j4 = (const float4*)(zjs + (size_t)p * DIMK);
    const float4* i4 = (const float4*)(zis + (size_t)p * DIMK);
    float4 ja = j4[lane], jb = j4[lane + 32];
    float4 ia = i4[lane], ib = i4[lane + 32];
    float ssj = ja.x*ja.x+ja.y*ja.y+ja.z*ja.z+ja.w*ja.w + jb.x*jb.x+jb.y*jb.y+jb.z*jb.z+jb.w*jb.w;
    float ssi = ia.x*ia.x+ia.y*ia.y+ia.z*ia.z+ia.w*ia.w + ib.x*ib.x+ib.y*ib.y+ib.z*ib.z+ib.w*ib.w;
    float dot = ja.x*ia.x+ja.y*ia.y+ja.z*ia.z+ja.w*ia.w + jb.x*ib.x+jb.y*ib.y+jb.z*ib.z+jb.w*ib.w;
    #pragma unroll
    for (int o = 16; o >= 1; o >>= 1) {
        ssj += __shfl_xor_sync(0xFFFFFFFFu, ssj, o);
        ssi += __shfl_xor_sync(0xFFFFFFFFu, ssi, o);
        dot += __shfl_xor_sync(0xFFFFFFFFu, dot, o);
    }
    float rj = rsqrtf(ssj), ri = rsqrtf(ssi);
    float rnj = rj * QSCALE, rni = ri * QSCALE;
    unsigned* dj = (unsigned*)(g_fp8 + (size_t)p * DIMK);
    unsigned* di = (unsigned*)(g_fp8 + (size_t)(p + NBATCH) * DIMK);
    dj[lane]      = (unsigned)pk_e4m3(ja.x*rnj, ja.y*rnj) | ((unsigned)pk_e4m3(ja.z*rnj, ja.w*rnj) << 16);
    dj[lane + 32] = (unsigned)pk_e4m3(jb.x*rnj, jb.y*rnj) | ((unsigned)pk_e4m3(jb.z*rnj, jb.w*rnj) << 16);
    di[lane]      = (unsigned)pk_e4m3(ia.x*rni, ia.y*rni) | ((unsigned)pk_e4m3(ia.z*rni, ia.w*rni) << 16);
    di[lane + 32] = (unsigned)pk_e4m3(ib.x*rni, ib.y*rni) | ((unsigned)pk_e4m3(ib.z*rni, ib.w*rni) << 16);
    if (lane == 0) {
        float pos = dot * rj * ri;
        g_pos[p] = pos;
        g_pos[p + NBATCH] = pos;
    }
}

// ---------------- kernel 2: symmetric FP8 MMA Gram + exp + row/col sums ----
// Upper-triangle tiles (2080), enumerated row-major: row I has tiles
// J = I..63. Grid 296 = 2 CTAs/SM slot (b and b+148 share an SM via the
// classic bid%148 LUT). Sizes: blocks 0..287 -> 7 tiles, 288..295 -> 8
// (slots 140..147 host 7+8=15, others 14). Tile (I,J): row-sums -> key J,
// col-sums -> key I (I!=J).
#define SMI   0
#define SMJ   32768
#define BBUF  32768
#define SMEM_TOTAL (32768 * 3)

static __device__ __forceinline__ void load_tile(unsigned dstbase, int band, int tid) {
    const char* src = (const char*)g_fp8 + (size_t)band * 128 * 256;
    #pragma unroll
    for (int i = 0; i < 8; i++) {
        int idx = tid + i * 256;
        int row = idx >> 4, u = idx & 15;
        CP_ASYNC16(dstbase + row * 256 + ((u ^ (row & 7)) << 4),
                   src + (size_t)row * 256 + u * 16);
    }
}

__global__ void __launch_bounds__(256, 2) ntx_main() {
    extern __shared__ char smem[];
    unsigned sb = smem_u32(smem);
    __shared__ float s_roww[4][128];
    __shared__ float s_colw[2][128];

    int tid = threadIdx.x, wid = tid >> 5, lane = tid & 31;
    int bx = blockIdx.x;
    int t0  = 7 * bx + (bx > 288 ? bx - 288 : 0);
    int cnt = 7 + (bx >= 288 ? 1 : 0);

    // decode starting (I, J) from triangular row-major index t0
    int I = (int)((129.0f - sqrtf(16641.0f - 8.0f * (float)t0)) * 0.5f);
    while (I * (129 - I) / 2 > t0) I--;
    while ((I + 1) * (128 - I) / 2 <= t0) I++;
    int J = I + (t0 - I * (129 - I) / 2);

    int wm = (wid & 1) * 64;
    int wn = (wid >> 1) * 32;
    int trow  = lane >> 2;
    int tcol2 = lane & 3;
    int sw    = lane & 7;
    int rowinA = ((lane >> 3) & 1) * 8 + (lane & 7);
    int kbA    = lane >> 4;
    int rowinB = (lane >> 4) * 8 + (lane & 7);
    int kbB    = (lane >> 3) & 1;

    unsigned abyte[4], bbyte[2];
    #pragma unroll
    for (int mt = 0; mt < 4; mt++) abyte[mt] = (unsigned)((wm + mt * 16 + rowinA) * 256);
    #pragma unroll
    for (int ng = 0; ng < 2; ng++)  bbyte[ng] = (unsigned)((wn + ng * 16 + rowinB) * 256);

    load_tile(sb + SMI, I, tid);
    load_tile(sb + SMJ, J, tid);
    CP_ASYNC_COMMIT();
    int curI = I;

    for (int k = 0; k < cnt; k++) {
        if (I != curI) {                       // band switch
            load_tile(sb + SMI, I, tid);
            CP_ASYNC_COMMIT();
            curI = I;
        }
        if (k + 1 < cnt) {                     // prefetch next J tile
            int In = I, Jn = J + 1;
            if (Jn == 64) { In = I + 1; Jn = In; }
            load_tile(sb + SMJ + (unsigned)((k + 1) & 1) * BBUF, Jn, tid);
            CP_ASYNC_COMMIT();
            asm volatile("cp.async.wait_group 1;" ::: "memory");
        } else {
            asm volatile("cp.async.wait_group 0;" ::: "memory");
        }
        __syncthreads();

        unsigned curB = sb + SMJ + (unsigned)(k & 1) * BBUF;

        float acc[4][4][4];
        #pragma unroll
        for (int mt = 0; mt < 4; mt++)
            #pragma unroll
            for (int nt = 0; nt < 4; nt++)
                #pragma unroll
                for (int e = 0; e < 4; e++) acc[mt][nt][e] = 0.f;

        #pragma unroll
        for (int ks = 0; ks < 8; ks++) {
            unsigned koffA = (unsigned)(((ks * 2 + kbA) ^ sw) << 4);
            unsigned koffB = (unsigned)(((ks * 2 + kbB) ^ sw) << 4);
            unsigned a0[4], a1[4], a2[4], a3[4];
            #pragma unroll
            for (int mt = 0; mt < 4; mt++)
                LDSM_X4(a0[mt], a1[mt], a2[mt], a3[mt], sb + SMI + abyte[mt] + koffA);
            unsigned b0[2], b1[2], b2[2], b3[2];
            #pragma unroll
            for (int ng = 0; ng < 2; ng++)
                LDSM_X4(b0[ng], b1[ng], b2[ng], b3[ng], curB + bbyte[ng] + koffB);
            #pragma unroll
            for (int mt = 0; mt < 4; mt++) {
                MMA_FP8(acc[mt][0][0], acc[mt][0][1], acc[mt][0][2], acc[mt][0][3],
                        a0[mt], a1[mt], a2[mt], a3[mt], b0[0], b1[0]);
                MMA_FP8(acc[mt][1][0], acc[mt][1][1], acc[mt][1][2], acc[mt][1][3],
                        a0[mt], a1[mt], a2[mt], a3[mt], b2[0], b3[0]);
                MMA_FP8(acc[mt][2][0], acc[mt][2][1], acc[mt][2][2], acc[mt][2][3],
                        a0[mt], a1[mt], a2[mt], a3[mt], b0[1], b1[1]);
                MMA_FP8(acc[mt][3][0], acc[mt][3][1], acc[mt][3][2], acc[mt][3][3],
                        a0[mt], a1[mt], a2[mt], a3[mt], b2[1], b3[1]);
            }
        }

        // epilogue: exp(acc * 2/QSCALE^2), mask self-diagonal, row+col partials
        bool diag = (I == J);
        float rsum[4][2], csum[4][2];
        #pragma unroll
        for (int x = 0; x < 4; x++) { rsum[x][0]=rsum[x][1]=csum[x][0]=csum[x][1]=0.f; }
        #pragma unroll
        for (int mt = 0; mt < 4; mt++) {
            int r0 = wm + mt * 16 + trow;
            #pragma unroll
            for (int nt = 0; nt < 4; nt++) {
                int c0 = wn + nt * 8 + tcol2 * 2;
                float e00 = __expf(EPSCL * acc[mt][nt][0]);
                float e01 = __expf(EPSCL * acc[mt][nt][1]);
                float e10 = __expf(EPSCL * acc[mt][nt][2]);
                float e11 = __expf(EPSCL * acc[mt][nt][3]);
                if (diag) {
                    if (r0 == c0)         e00 = 0.f;
                    if (r0 == c0 + 1)     e01 = 0.f;
                    if (r0 + 8 == c0)     e10 = 0.f;
                    if (r0 + 8 == c0 + 1) e11 = 0.f;
                }
                rsum[mt][0] += e00 + e01;
                rsum[mt][1] += e10 + e11;
                csum[nt][0] += e00 + e10;
                csum[nt][1] += e01 + e11;
            }
        }
        #pragma unroll
        for (int mt = 0; mt < 4; mt++)
            #pragma unroll
            for (int hf = 0; hf < 2; hf++) {
                float v = rsum[mt][hf];
                v += __shfl_xor_sync(0xFFFFFFFFu, v, 1);
                v += __shfl_xor_sync(0xFFFFFFFFu, v, 2);
                if ((lane & 3) == 0)
                    s_roww[wid >> 1][wm + mt * 16 + hf * 8 + trow] = v;
            }
        #pragma unroll
        for (int nt = 0; nt < 4; nt++)
            #pragma unroll
            for (int j = 0; j < 2; j++) {
                float v = csum[nt][j];
                v += __shfl_xor_sync(0xFFFFFFFFu, v, 4);
                v += __shfl_xor_sync(0xFFFFFFFFu, v, 8);
                v += __shfl_xor_sync(0xFFFFFFFFu, v, 16);
                if (lane < 4)
                    s_colw[wid & 1][wn + nt * 8 + lane * 2 + j] = v;
            }
        __syncthreads();

        if (tid < 128) {
            float rv = s_roww[0][tid] + s_roww[1][tid] + s_roww[2][tid] + s_roww[3][tid];
            g_scatter[(size_t)J * TWO_N + I * 128 + tid] = rv;
            if (!diag) {
                float cv = s_colw[0][tid] + s_colw[1][tid];
                g_scatter[(size_t)I * TWO_N + J * 128 + tid] = cv;
            }
        }

        // advance (I, J) row-major within upper triangle
        J++;
        if (J == 64) { I++; J = I; }
    }
}

// ---------------- kernel 3: per-row loss partials + last-block finalize ----
__global__ void ntx_fin(float* __restrict__ out) {
    __shared__ float sh[256];
    __shared__ int s_last;
    int tid = threadIdx.x;
    int i = blockIdx.x * 256 + tid;
    float rs = 0.f;
    #pragma unroll
    for (int k = 0; k < 64; k++) rs += g_scatter[(size_t)k * TWO_N + i];
    sh[tid] = logf(rs) - INV_TEMP * g_pos[i];
    __syncthreads();
    for (int s = 128; s >= 1; s >>= 1) {
        if (tid < s) sh[tid] += sh[tid + s];
        __syncthreads();
    }
    if (tid == 0) {
        g_partial[blockIdx.x] = sh[0];
        __threadfence();
        unsigned old = atomicAdd(&g_ctr, 1u);
        s_last = (old == 31u);
    }
    __syncthreads();
    if (s_last && tid < 32) {
        float v = g_partial[tid];
        #pragma unroll
        for (int o = 16; o >= 1; o >>= 1) v += __shfl_xor_sync(0xFFFFFFFFu, v, o);
        if (tid == 0) out[0] = v / (float)TWO_N;
    }
}

extern "C" void kernel_launch(void* const* d_in, const int* in_sizes, int n_in,
                              void* d_out, int out_size) {
    const float* zis = (const float*)d_in[0];
    const float* zjs = (const float*)d_in[1];
    float* out = (float*)d_out;
    (void)in_sizes; (void)n_in; (void)out_size;

    cudaFuncSetAttribute(ntx_main, cudaFuncAttributeMaxDynamicSharedMemorySize,
                         SMEM_TOTAL);

    ntx_norm<<<NBATCH / 8, 256>>>(zis, zjs);
    ntx_main<<<296, 256, SMEM_TOTAL>>>();
    ntx_fin<<<32, 256>>>(out);
}

// round 11
// speedup vs baseline: 2.5608x; 1.0956x over previous
#include <cuda_runtime.h>
#include <cuda_fp16.h>
#include <math.h>

#define NBATCH 4096
#define TWO_N  8192
#define DIMK   256
#define INV_TEMP 2.0f
#define QSCALE 16.0f            // fp8 quantization scale
#define EPSCL  (2.0f / 256.0f)  // epilogue: INV_TEMP / QSCALE^2

// ---------------- device scratch (no allocs allowed) ----------------
__device__ unsigned char g_fp8[TWO_N * DIMK]; // normalized reps e4m3*16 (2 MB)
__device__ float    g_pos[TWO_N];             // positive-pair cosine (fp32 exact)
__device__ float    g_scatter[64 * TWO_N];    // per-(row, key) partial sums (2 MB)
__device__ float    g_partial[32];            // finalize partials
__device__ unsigned g_ctr;                    // last-block-done counter

// ---------------- PTX helpers (base sm_103 target only) ----------------
static __device__ __forceinline__ unsigned smem_u32(const void* p) {
    unsigned a;
    asm("{ .reg .u64 t; cvta.to.shared.u64 t, %1; cvt.u32.u64 %0, t; }" : "=r"(a) : "l"(p));
    return a;
}

// pack two f32 -> e4m3x2 (lo in low byte)
static __device__ __forceinline__ unsigned short pk_e4m3(float lo, float hi) {
    unsigned short r;
    asm("cvt.rn.satfinite.e4m3x2.f32 %0, %2, %1;" : "=h"(r) : "f"(lo), "f"(hi));
    return r;
}

#define CP_ASYNC16(dst, src) \
    asm volatile("cp.async.cg.shared.global [%0], [%1], 16;" :: "r"(dst), "l"(src) : "memory")
#define CP_ASYNC_COMMIT() asm volatile("cp.async.commit_group;" ::: "memory")

#define LDSM_X4(r0, r1, r2, r3, addr) \
    asm volatile("ldmatrix.sync.aligned.m8n8.x4.shared.b16 {%0,%1,%2,%3}, [%4];" \
        : "=r"(r0), "=r"(r1), "=r"(r2), "=r"(r3) : "r"(addr))

// fp8 e4m3 MMA: m16n8k32, f16 accumulate (Ada-style 2x rate on legacy pipe)
#define MMA_FP8_H(c01, c23, a0, a1, a2, a3, b0, b1) \
    asm volatile("mma.sync.aligned.m16n8k32.row.col.f16.e4m3.e4m3.f16 " \
        "{%0,%1}, {%2,%3,%4,%5}, {%6,%7}, {%0,%1};" \
        : "+r"(c01), "+r"(c23) \
        : "r"(a0), "r"(a1), "r"(a2), "r"(a3), "r"(b0), "r"(b1))

// ---------------- kernel 1: normalize + positive pairs -> fp8 ----------------
__global__ void ntx_norm(const float* __restrict__ zis,
                         const float* __restrict__ zjs) {
    if (blockIdx.x == 0 && threadIdx.x == 0) g_ctr = 0;   // reset finalize counter
    int p    = blockIdx.x * 8 + (threadIdx.x >> 5);
    int lane = threadIdx.x & 31;
    const float4* j4 = (const float4*)(zjs + (size_t)p * DIMK);
    const float4* i4 = (const float4*)(zis + (size_t)p * DIMK);
    float4 ja = j4[lane], jb = j4[lane + 32];
    float4 ia = i4[lane], ib = i4[lane + 32];
    float ssj = ja.x*ja.x+ja.y*ja.y+ja.z*ja.z+ja.w*ja.w + jb.x*jb.x+jb.y*jb.y+jb.z*jb.z+jb.w*jb.w;
    float ssi = ia.x*ia.x+ia.y*ia.y+ia.z*ia.z+ia.w*ia.w + ib.x*ib.x+ib.y*ib.y+ib.z*ib.z+ib.w*ib.w;
    float dot = ja.x*ia.x+ja.y*ia.y+ja.z*ia.z+ja.w*ia.w + jb.x*ib.x+jb.y*ib.y+jb.z*ib.z+jb.w*ib.w;
    #pragma unroll
    for (int o = 16; o >= 1; o >>= 1) {
        ssj += __shfl_xor_sync(0xFFFFFFFFu, ssj, o);
        ssi += __shfl_xor_sync(0xFFFFFFFFu, ssi, o);
        dot += __shfl_xor_sync(0xFFFFFFFFu, dot, o);
    }
    float rj = rsqrtf(ssj), ri = rsqrtf(ssi);
    float rnj = rj * QSCALE, rni = ri * QSCALE;
    unsigned* dj = (unsigned*)(g_fp8 + (size_t)p * DIMK);
    unsigned* di = (unsigned*)(g_fp8 + (size_t)(p + NBATCH) * DIMK);
    dj[lane]      = (unsigned)pk_e4m3(ja.x*rnj, ja.y*rnj) | ((unsigned)pk_e4m3(ja.z*rnj, ja.w*rnj) << 16);
    dj[lane + 32] = (unsigned)pk_e4m3(jb.x*rnj, jb.y*rnj) | ((unsigned)pk_e4m3(jb.z*rnj, jb.w*rnj) << 16);
    di[lane]      = (unsigned)pk_e4m3(ia.x*rni, ia.y*rni) | ((unsigned)pk_e4m3(ia.z*rni, ia.w*rni) << 16);
    di[lane + 32] = (unsigned)pk_e4m3(ib.x*rni, ib.y*rni) | ((unsigned)pk_e4m3(ib.z*rni, ib.w*rni) << 16);
    if (lane == 0) {
        float pos = dot * rj * ri;
        g_pos[p] = pos;
        g_pos[p + NBATCH] = pos;
    }
}

// ---------------- kernel 2: symmetric FP8 MMA Gram + exp + row/col sums ----
// Upper-triangle tiles (2080), row-major. Grid 296 = 2 CTAs/SM slot.
// Tile (I,J): row-sums -> key J, col-sums -> key I (I!=J).
#define SMI   0
#define SMJ   32768
#define BBUF  32768
#define SMEM_TOTAL (32768 * 3)

static __device__ __forceinline__ void load_tile(unsigned dstbase, int band, int tid) {
    const char* src = (const char*)g_fp8 + (size_t)band * 128 * 256;
    #pragma unroll
    for (int i = 0; i < 8; i++) {
        int idx = tid + i * 256;
        int row = idx >> 4, u = idx & 15;
        CP_ASYNC16(dstbase + row * 256 + ((u ^ (row & 7)) << 4),
                   src + (size_t)row * 256 + u * 16);
    }
}

__global__ void __launch_bounds__(256, 2) ntx_main() {
    extern __shared__ char smem[];
    unsigned sb = smem_u32(smem);
    __shared__ float s_roww[4][128];
    __shared__ float s_colw[2][128];

    int tid = threadIdx.x, wid = tid >> 5, lane = tid & 31;
    int bx = blockIdx.x;
    int t0  = 7 * bx + (bx > 288 ? bx - 288 : 0);
    int cnt = 7 + (bx >= 288 ? 1 : 0);

    // decode starting (I, J) from triangular row-major index t0
    int I = (int)((129.0f - sqrtf(16641.0f - 8.0f * (float)t0)) * 0.5f);
    while (I * (129 - I) / 2 > t0) I--;
    while ((I + 1) * (128 - I) / 2 <= t0) I++;
    int J = I + (t0 - I * (129 - I) / 2);

    int wm = (wid & 1) * 64;
    int wn = (wid >> 1) * 32;
    int trow  = lane >> 2;
    int tcol2 = lane & 3;
    int sw    = lane & 7;
    int rowinA = ((lane >> 3) & 1) * 8 + (lane & 7);
    int kbA    = lane >> 4;
    int rowinB = (lane >> 4) * 8 + (lane & 7);
    int kbB    = (lane >> 3) & 1;

    unsigned abyte[4], bbyte[2];
    #pragma unroll
    for (int mt = 0; mt < 4; mt++) abyte[mt] = (unsigned)((wm + mt * 16 + rowinA) * 256);
    #pragma unroll
    for (int ng = 0; ng < 2; ng++)  bbyte[ng] = (unsigned)((wn + ng * 16 + rowinB) * 256);

    load_tile(sb + SMI, I, tid);
    load_tile(sb + SMJ, J, tid);
    CP_ASYNC_COMMIT();
    int curI = I;

    for (int k = 0; k < cnt; k++) {
        if (I != curI) {                       // band switch
            load_tile(sb + SMI, I, tid);
            CP_ASYNC_COMMIT();
            curI = I;
        }
        if (k + 1 < cnt) {                     // prefetch next J tile
            int In = I, Jn = J + 1;
            if (Jn == 64) { In = I + 1; Jn = In; }
            load_tile(sb + SMJ + (unsigned)((k + 1) & 1) * BBUF, Jn, tid);
            CP_ASYNC_COMMIT();
            asm volatile("cp.async.wait_group 1;" ::: "memory");
        } else {
            asm volatile("cp.async.wait_group 0;" ::: "memory");
        }
        __syncthreads();

        unsigned curB = sb + SMJ + (unsigned)(k & 1) * BBUF;

        // f16x2 accumulators: [mt][nt][0]=rows trow cols (2c,2c+1), [1]=row trow+8
        unsigned acc[4][4][2];
        #pragma unroll
        for (int mt = 0; mt < 4; mt++)
            #pragma unroll
            for (int nt = 0; nt < 4; nt++) { acc[mt][nt][0] = 0u; acc[mt][nt][1] = 0u; }

        #pragma unroll
        for (int ks = 0; ks < 8; ks++) {
            unsigned koffA = (unsigned)(((ks * 2 + kbA) ^ sw) << 4);
            unsigned koffB = (unsigned)(((ks * 2 + kbB) ^ sw) << 4);
            unsigned a0[4], a1[4], a2[4], a3[4];
            #pragma unroll
            for (int mt = 0; mt < 4; mt++)
                LDSM_X4(a0[mt], a1[mt], a2[mt], a3[mt], sb + SMI + abyte[mt] + koffA);
            unsigned b0[2], b1[2], b2[2], b3[2];
            #pragma unroll
            for (int ng = 0; ng < 2; ng++)
                LDSM_X4(b0[ng], b1[ng], b2[ng], b3[ng], curB + bbyte[ng] + koffB);
            #pragma unroll
            for (int mt = 0; mt < 4; mt++) {
                MMA_FP8_H(acc[mt][0][0], acc[mt][0][1],
                          a0[mt], a1[mt], a2[mt], a3[mt], b0[0], b1[0]);
                MMA_FP8_H(acc[mt][1][0], acc[mt][1][1],
                          a0[mt], a1[mt], a2[mt], a3[mt], b2[0], b3[0]);
                MMA_FP8_H(acc[mt][2][0], acc[mt][2][1],
                          a0[mt], a1[mt], a2[mt], a3[mt], b0[1], b1[1]);
                MMA_FP8_H(acc[mt][3][0], acc[mt][3][1],
                          a0[mt], a1[mt], a2[mt], a3[mt], b2[1], b3[1]);
            }
        }

        // epilogue: exp(acc * 2/QSCALE^2), mask self-diagonal, row+col partials
        bool diag = (I == J);
        float rsum[4][2], csum[4][2];
        #pragma unroll
        for (int x = 0; x < 4; x++) { rsum[x][0]=rsum[x][1]=csum[x][0]=csum[x][1]=0.f; }
        #pragma unroll
        for (int mt = 0; mt < 4; mt++) {
            int r0 = wm + mt * 16 + trow;
            #pragma unroll
            for (int nt = 0; nt < 4; nt++) {
                int c0 = wn + nt * 8 + tcol2 * 2;
                float2 lo = __half22float2(*(__half2*)&acc[mt][nt][0]);
                float2 hi = __half22float2(*(__half2*)&acc[mt][nt][1]);
                float e00 = __expf(EPSCL * lo.x);
                float e01 = __expf(EPSCL * lo.y);
                float e10 = __expf(EPSCL * hi.x);
                float e11 = __expf(EPSCL * hi.y);
                if (diag) {
                    if (r0 == c0)         e00 = 0.f;
                    if (r0 == c0 + 1)     e01 = 0.f;
                    if (r0 + 8 == c0)     e10 = 0.f;
                    if (r0 + 8 == c0 + 1) e11 = 0.f;
                }
                rsum[mt][0] += e00 + e01;
                rsum[mt][1] += e10 + e11;
                csum[nt][0] += e00 + e10;
                csum[nt][1] += e01 + e11;
            }
        }
        #pragma unroll
        for (int mt = 0; mt < 4; mt++)
            #pragma unroll
            for (int hf = 0; hf < 2; hf++) {
                float v = rsum[mt][hf];
                v += __shfl_xor_sync(0xFFFFFFFFu, v, 1);
                v += __shfl_xor_sync(0xFFFFFFFFu, v, 2);
                if ((lane & 3) == 0)
                    s_roww[wid >> 1][wm + mt * 16 + hf * 8 + trow] = v;
            }
        #pragma unroll
        for (int nt = 0; nt < 4; nt++)
            #pragma unroll
            for (int j = 0; j < 2; j++) {
                float v = csum[nt][j];
                v += __shfl_xor_sync(0xFFFFFFFFu, v, 4);
                v += __shfl_xor_sync(0xFFFFFFFFu, v, 8);
                v += __shfl_xor_sync(0xFFFFFFFFu, v, 16);
                if (lane < 4)
                    s_colw[wid & 1][wn + nt * 8 + lane * 2 + j] = v;
            }
        __syncthreads();

        if (tid < 128) {
            float rv = s_roww[0][tid] + s_roww[1][tid] + s_roww[2][tid] + s_roww[3][tid];
            g_scatter[(size_t)J * TWO_N + I * 128 + tid] = rv;
            if (!diag) {
                float cv = s_colw[0][tid] + s_colw[1][tid];
                g_scatter[(size_t)I * TWO_N + J * 128 + tid] = cv;
            }
        }

        // advance (I, J) row-major within upper triangle
        J++;
        if (J == 64) { I++; J = I; }
    }
}

// ---------------- kernel 3: per-row loss partials + last-block finalize ----
__global__ void ntx_fin(float* __restrict__ out) {
    __shared__ float sh[256];
    __shared__ int s_last;
    int tid = threadIdx.x;
    int i = blockIdx.x * 256 + tid;
    float rs = 0.f;
    #pragma unroll
    for (int k = 0; k < 64; k++) rs += g_scatter[(size_t)k * TWO_N + i];
    sh[tid] = logf(rs) - INV_TEMP * g_pos[i];
    __syncthreads();
    for (int s = 128; s >= 1; s >>= 1) {
        if (tid < s) sh[tid] += sh[tid + s];
        __syncthreads();
    }
    if (tid == 0) {
        g_partial[blockIdx.x] = sh[0];
        __threadfence();
        unsigned old = atomicAdd(&g_ctr, 1u);
        s_last = (old == 31u);
    }
    __syncthreads();
    if (s_last && tid < 32) {
        float v = g_partial[tid];
        #pragma unroll
        for (int o = 16; o >= 1; o >>= 1) v += __shfl_xor_sync(0xFFFFFFFFu, v, o);
        if (tid == 0) out[0] = v / (float)TWO_N;
    }
}

extern "C" void kernel_launch(void* const* d_in, const int* in_sizes, int n_in,
                              void* d_out, int out_size) {
    const float* zis = (const float*)d_in[0];
    const float* zjs = (const float*)d_in[1];
    float* out = (float*)d_out;
    (void)in_sizes; (void)n_in; (void)out_size;

    cudaFuncSetAttribute(ntx_main, cudaFuncAttributeMaxDynamicSharedMemorySize,
                         SMEM_TOTAL);

    ntx_norm<<<NBATCH / 8, 256>>>(zis, zjs);
    ntx_main<<<296, 256, SMEM_TOTAL>>>();
    ntx_fin<<<32, 256>>>(out);
}